// round 3
// baseline (speedup 1.0000x reference)
#include <cuda_runtime.h>
#include <cstdint>

// Problem constants (from reference): B=8, N=65536, C=256, NPOINT=1024
#define BB        8
#define NN        65536
#define CC        256
#define NPOINTS   1024
#define CHUNKS    16                  // blocks per batch (16*8=128 blocks <= 148 SMs -> all resident)
#define TFPS      512                 // threads per FPS block
#define PPB       (NN / CHUNKS)       // 4096 points per block
#define PPT       (PPB / TFPS)        // 8 points per thread

// Per-(batch, iteration) reduction slots. Fresh slot per iteration -> no phase hazards.
__device__ unsigned long long g_slot[BB][NPOINTS];
__device__ unsigned int       g_cnt [BB][NPOINTS];
__device__ int                g_inds[BB][NPOINTS];

struct InitFar { int v[BB]; };

// ---------------------------------------------------------------------------
// Zero the reduction slots (scratch persists across graph replays -> must reset)
// ---------------------------------------------------------------------------
__global__ void init_kernel() {
    int i = blockIdx.x * blockDim.x + threadIdx.x;
    if (i < BB * NPOINTS) {
        (&g_slot[0][0])[i] = 0ull;
        (&g_cnt [0][0])[i] = 0u;
    }
}

// ---------------------------------------------------------------------------
// FPS: one batch split across CHUNKS blocks; points + running distances live
// in registers. Per iteration: local min-update + argmax, warp/block reduce,
// per-batch 64-bit atomicMax reduction, arrival-counter spin, broadcast.
// Packing: (float_bits(dist) << 32) | ~idx  -> max picks largest dist, and on
// ties the SMALLEST index (matches jnp.argmax first-occurrence semantics).
// ---------------------------------------------------------------------------
__global__ __launch_bounds__(TFPS, 1)
void fps_kernel(const float* __restrict__ xyz, InitFar init) {
    const int b     = blockIdx.y;
    const int chunk = blockIdx.x;
    const int t     = threadIdx.x;
    const int lane  = t & 31;
    const int warp  = t >> 5;
    const int base  = chunk * PPB;

    const float* __restrict__ xb = xyz + (size_t)b * NN * 3;

    float    px[PPT], py[PPT], pz[PPT], dist[PPT];
    unsigned ienc[PPT];
#pragma unroll
    for (int k = 0; k < PPT; ++k) {
        const int p = base + k * TFPS + t;
        const float* q = xb + 3 * (size_t)p;
        px[k] = q[0]; py[k] = q[1]; pz[k] = q[2];
        dist[k] = 1e10f;
        ienc[k] = ~(unsigned)p;
    }

    __shared__ unsigned long long s_red[TFPS / 32];
    __shared__ int s_far;

    int far = init.v[b];

    for (int it = 0; it < NPOINTS; ++it) {
        // Record the index chosen at the START of the step (matches lax.scan ys)
        if (chunk == 0 && t == 0) g_inds[b][it] = far;

        // Centroid broadcast load (one wavefront, L2 hit)
        const float* cq = xb + 3 * (size_t)far;
        const float cx = __ldg(cq + 0);
        const float cy = __ldg(cq + 1);
        const float cz = __ldg(cq + 2);

        unsigned long long best = 0ull;
#pragma unroll
        for (int k = 0; k < PPT; ++k) {
            // Match XLA (no FP contraction): sub, mul, (d0+d1)+d2, all round-to-nearest
            const float dx = __fsub_rn(px[k], cx);
            const float dy = __fsub_rn(py[k], cy);
            const float dz = __fsub_rn(pz[k], cz);
            const float d  = __fadd_rn(__fadd_rn(__fmul_rn(dx, dx), __fmul_rn(dy, dy)),
                                       __fmul_rn(dz, dz));
            const float nd = fminf(dist[k], d);
            dist[k] = nd;
            const unsigned long long pk =
                ((unsigned long long)__float_as_uint(nd) << 32) | (unsigned long long)ienc[k];
            best = (best < pk) ? pk : best;
        }

        // Warp reduce (max)
#pragma unroll
        for (int off = 16; off > 0; off >>= 1) {
            const unsigned long long o = __shfl_xor_sync(0xFFFFFFFFu, best, off);
            best = (best < o) ? o : best;
        }
        if (lane == 0) s_red[warp] = best;
        __syncthreads();

        if (t == 0) {
            unsigned long long blk = s_red[0];
#pragma unroll
            for (int i = 1; i < TFPS / 32; ++i) blk = (blk < s_red[i]) ? s_red[i] : blk;

            atomicMax(&g_slot[b][it], blk);
            __threadfence();
            atomicAdd(&g_cnt[b][it], 1u);

            // Spin until all CHUNKS blocks of this batch have contributed.
            while (*(volatile unsigned*)&g_cnt[b][it] < (unsigned)CHUNKS) {
                __nanosleep(32);
            }
            __threadfence();
            const unsigned long long w = atomicMax(&g_slot[b][it], 0ull);  // atomic read
            s_far = (int)(~(unsigned)(w & 0xFFFFFFFFull));
        }
        __syncthreads();
        far = s_far;
    }
}

// ---------------------------------------------------------------------------
// Gather outputs. d_out (float32) layout, concatenated in reference order:
//   [0)                    new_xyz      (B, NPOINT, 3)
//   [B*NPOINT*3)           new_features (B, C, NPOINT)
//   [.. + B*C*NPOINT)      sample_inds  (B, NPOINT)  (indices as float)
// ---------------------------------------------------------------------------
__global__ void gather_kernel(const float* __restrict__ xyz,
                              const float* __restrict__ feat,
                              float* __restrict__ out) {
    const int b = blockIdx.x;
    const int c = blockIdx.y;

    float* out_xyz  = out;
    float* out_feat = out + (size_t)BB * NPOINTS * 3;
    float* out_inds = out_feat + (size_t)BB * CC * NPOINTS;

    const float* frow = feat + ((size_t)b * CC + c) * NN;
    float*       orow = out_feat + ((size_t)b * CC + c) * NPOINTS;

    for (int j = threadIdx.x; j < NPOINTS; j += blockDim.x) {
        const int idx = g_inds[b][j];
        orow[j] = frow[idx];
        if (c == 0) {
            out_inds[(size_t)b * NPOINTS + j] = (float)idx;
            const float* q = xyz + ((size_t)b * NN + idx) * 3;
            float* o = out_xyz + ((size_t)b * NPOINTS + j) * 3;
            o[0] = q[0]; o[1] = q[1]; o[2] = q[2];
        }
    }
}

// ---------------------------------------------------------------------------
// Host: reproduce jax.random.randint(jax.random.key(1), (8,), 0, 65536)
// under jax_threefry_partitionable=True (default since JAX 0.5.0).
//
// randint internally does:
//   k1, k2 = split(key)                       # foldlike split
//   higher = random_bits(k1, 32, (8,))        # irrelevant: multiplier == 0
//   lower  = random_bits(k2, 32, (8,))
//   idx    = lower & 0xFFFF                   # span 2^16 -> (2^30 % span)==0
//
// foldlike split of key (0,1):  newkey_j = threefry2x32((0,1), (0, j))
// partitionable 32-bit bits:    bits[b] = o0 ^ o1 of threefry2x32(k2, (0, b))
// ---------------------------------------------------------------------------
static void threefry2x32_host(uint32_t k0, uint32_t k1, uint32_t c0, uint32_t c1,
                              uint32_t* o0, uint32_t* o1) {
    const uint32_t ks[3] = { k0, k1, k0 ^ k1 ^ 0x1BD11BDAu };
    static const int rot0[4] = {13, 15, 26, 6};
    static const int rot1[4] = {17, 29, 16, 24};
    uint32_t x0 = c0 + ks[0];
    uint32_t x1 = c1 + ks[1];
    for (int i = 0; i < 5; ++i) {
        const int* rr = (i % 2 == 0) ? rot0 : rot1;
        for (int j = 0; j < 4; ++j) {
            x0 += x1;
            x1 = (x1 << rr[j]) | (x1 >> (32 - rr[j]));
            x1 ^= x0;
        }
        x0 += ks[(i + 1) % 3];
        x1 += ks[(i + 2) % 3] + (uint32_t)(i + 1);
    }
    *o0 = x0; *o1 = x1;
}

extern "C" void kernel_launch(void* const* d_in, const int* in_sizes, int n_in,
                              void* d_out, int out_size) {
    (void)in_sizes; (void)n_in; (void)out_size;
    const float* xyz  = (const float*)d_in[0];
    const float* feat = (const float*)d_in[1];

    // Step 1: foldlike split of key(1) = (0,1): k2 = threefry2x32((0,1), (0,1))
    uint32_t k2a, k2b;
    threefry2x32_host(0u, 1u, 0u, 1u, &k2a, &k2b);

    // Step 2: partitionable random_bits(k2, 32, (8,)) -> xor combine -> & 0xFFFF
    InitFar init;
    for (int b = 0; b < BB; ++b) {
        uint32_t o0, o1;
        threefry2x32_host(k2a, k2b, 0u, (uint32_t)b, &o0, &o1);
        init.v[b] = (int)((o0 ^ o1) & 0xFFFFu);
    }

    init_kernel<<<(BB * NPOINTS + 255) / 256, 256>>>();
    fps_kernel<<<dim3(CHUNKS, BB), TFPS>>>(xyz, init);
    gather_kernel<<<dim3(BB, CC), 256>>>(xyz, feat, (float*)d_out);
}